// round 4
// baseline (speedup 1.0000x reference)
#include <cuda_runtime.h>
#include <math.h>

// Problem constants (fixed shapes for this problem)
#define NMAX 100000
#define EMAX 800000
#define DIM  64

// Scratch (allocation-free rule: __device__ globals)
__device__ float g_Q[NMAX * DIM];
__device__ float g_K[NMAX * DIM];
__device__ float g_V[NMAX * DIM];
__device__ float g_Z[NMAX * 4];

// ---------------------------------------------------------------------------
// Kernel 1: zero wV accumulator (d_out) and Z
// ---------------------------------------------------------------------------
__global__ void init_kernel(float* __restrict__ out, int n) {
    int total = n * DIM;
    int zn = n * 4;
    for (int i = blockIdx.x * blockDim.x + threadIdx.x; i < total;
         i += gridDim.x * blockDim.x) {
        out[i] = 0.0f;
        if (i < zn) g_Z[i] = 0.0f;
    }
}

// ---------------------------------------------------------------------------
// Kernel 2: Q/K/V node projections.  y = x @ W.T  (W is [out][in], row-major)
// Warp handles 4 nodes; lane owns output dims (2l, 2l+1) as float2.
// W stored transposed in smem: sW[k*64 + o] = W[o][k]  (conflict-free float2)
// ---------------------------------------------------------------------------
__global__ __launch_bounds__(256) void qkv_kernel(
    const float* __restrict__ x,
    const float* __restrict__ Wq,
    const float* __restrict__ Wk,
    const float* __restrict__ Wv,
    int n)
{
    __shared__ float sWq[DIM * DIM];
    __shared__ float sWk[DIM * DIM];
    __shared__ float sWv[DIM * DIM];
    for (int i = threadIdx.x; i < DIM * DIM; i += blockDim.x) {
        int o = i >> 6, k = i & 63;
        sWq[k * 64 + o] = Wq[i];
        sWk[k * 64 + o] = Wk[i];
        sWv[k * 64 + o] = Wv[i];
    }
    __syncthreads();

    int warp = threadIdx.x >> 5;
    int l    = threadIdx.x & 31;
    int base = (blockIdx.x * 8 + warp) * 4;
    if (base >= n) return;

    const float2* x2  = (const float2*)x;
    const float2* Wq2 = (const float2*)sWq;
    const float2* Wk2 = (const float2*)sWk;
    const float2* Wv2 = (const float2*)sWv;

    float2 xr[4];
    int node[4];
#pragma unroll
    for (int i = 0; i < 4; i++) {
        node[i] = min(base + i, n - 1);
        xr[i]   = x2[node[i] * 32 + l];
    }

    float2 qa[4], ka[4], va[4];
#pragma unroll
    for (int i = 0; i < 4; i++) {
        qa[i] = make_float2(0.f, 0.f);
        ka[i] = make_float2(0.f, 0.f);
        va[i] = make_float2(0.f, 0.f);
    }

#pragma unroll 8
    for (int kk = 0; kk < DIM; kk++) {
        float2 wq = Wq2[kk * 32 + l];
        float2 wk = Wk2[kk * 32 + l];
        float2 wv = Wv2[kk * 32 + l];
#pragma unroll
        for (int i = 0; i < 4; i++) {
            float a = __shfl_sync(0xffffffffu,
                                  (kk & 1) ? xr[i].y : xr[i].x, kk >> 1);
            qa[i].x += a * wq.x; qa[i].y += a * wq.y;
            ka[i].x += a * wk.x; ka[i].y += a * wk.y;
            va[i].x += a * wv.x; va[i].y += a * wv.y;
        }
    }

    float2* Q2 = (float2*)g_Q;
    float2* K2 = (float2*)g_K;
    float2* V2 = (float2*)g_V;
#pragma unroll
    for (int i = 0; i < 4; i++) {
        if (base + i < n) {
            Q2[node[i] * 32 + l] = qa[i];
            K2[node[i] * 32 + l] = ka[i];
            V2[node[i] * 32 + l] = va[i];
        }
    }
}

// ---------------------------------------------------------------------------
// Kernel 3: fused edge projection + attention score + scatter.
//   Eproj = edge_attr @ We.T   (fused, never materialized)
//   t_h   = sum_{d in head} (K[src]*Q[dst]/4) * Eproj
//   s     = exp(clip(t_h, -5, 5))
//   wV[dst] += V[src]*s ; Z[dst,h] += s
// Warp handles 4 edges; lane owns dims (2l, 2l+1). Head = l>>3 (8 lanes/head).
// edge_index: int32 on device (JAX default config downgrades int64 -> int32).
// ---------------------------------------------------------------------------
__global__ __launch_bounds__(256) void edge_kernel(
    const float* __restrict__ ea,
    const int*   __restrict__ ei,   // [2, nE] int32: row0 = src, row1 = dst
    const float* __restrict__ We,
    float* __restrict__ out,        // wV accumulator [n, 64]
    int nE)
{
    __shared__ float sWe[DIM * DIM];
    for (int i = threadIdx.x; i < DIM * DIM; i += blockDim.x) {
        int o = i >> 6, k = i & 63;
        sWe[k * 64 + o] = We[i];
    }
    __syncthreads();

    const float2* W2  = (const float2*)sWe;
    const float2* ea2 = (const float2*)ea;
    const float2* Q2  = (const float2*)g_Q;
    const float2* K2  = (const float2*)g_K;
    const float2* V2  = (const float2*)g_V;

    int warp = threadIdx.x >> 5;
    int l    = threadIdx.x & 31;
    int head = l >> 3;

    int nTiles = (nE + 31) / 32;
    for (int tile = blockIdx.x; tile < nTiles; tile += gridDim.x) {
        int e0 = tile * 32 + warp * 4;

        float2 er[4], qv[4], kv[4], vv[4];
        int dst[4];
#pragma unroll
        for (int i = 0; i < 4; i++) {
            int e = min(e0 + i, nE - 1);
            int s = __ldg(&ei[e]);
            int d = __ldg(&ei[nE + e]);
            dst[i] = (e0 + i < nE) ? d : -1;
            er[i]  = ea2[e * 32 + l];
            qv[i]  = Q2[d * 32 + l];
            kv[i]  = K2[s * 32 + l];
            vv[i]  = V2[s * 32 + l];
        }

        float ex[4] = {0.f, 0.f, 0.f, 0.f};
        float ey[4] = {0.f, 0.f, 0.f, 0.f};
#pragma unroll 8
        for (int kk = 0; kk < DIM; kk++) {
            float2 w = W2[kk * 32 + l];
#pragma unroll
            for (int i = 0; i < 4; i++) {
                float a = __shfl_sync(0xffffffffu,
                                      (kk & 1) ? er[i].y : er[i].x, kk >> 1);
                ex[i] += a * w.x;
                ey[i] += a * w.y;
            }
        }

#pragma unroll
        for (int i = 0; i < 4; i++) {
            float t = qv[i].x * kv[i].x * ex[i] + qv[i].y * kv[i].y * ey[i];
            t *= 0.25f;
            // reduce over the 8-lane head group
            t += __shfl_xor_sync(0xffffffffu, t, 4);
            t += __shfl_xor_sync(0xffffffffu, t, 2);
            t += __shfl_xor_sync(0xffffffffu, t, 1);
            float sc = __expf(fminf(fmaxf(t, -5.0f), 5.0f));
            int d = dst[i];
            if (d >= 0) {
                atomicAdd(&out[d * 64 + 2 * l],     vv[i].x * sc);
                atomicAdd(&out[d * 64 + 2 * l + 1], vv[i].y * sc);
                if ((l & 7) == 0)
                    atomicAdd(&g_Z[d * 4 + head], sc);
            }
        }
    }
}

// ---------------------------------------------------------------------------
// Kernel 4: out = wV / (Z + 1e-6)
// ---------------------------------------------------------------------------
__global__ void fin_kernel(float* __restrict__ out, int n) {
    int total = n * DIM;
    for (int i = blockIdx.x * blockDim.x + threadIdx.x; i < total;
         i += gridDim.x * blockDim.x) {
        int node = i >> 6;
        int h    = (i >> 4) & 3;
        out[i] = out[i] / (g_Z[node * 4 + h] + 1e-6f);
    }
}

// ---------------------------------------------------------------------------
// Launch
// Inputs (metadata order): x, edge_attr, Wq, Wk, We, Wv, edge_index
// ---------------------------------------------------------------------------
extern "C" void kernel_launch(void* const* d_in, const int* in_sizes, int n_in,
                              void* d_out, int out_size) {
    const float* x   = (const float*)d_in[0];
    const float* ea  = (const float*)d_in[1];
    const float* Wq  = (const float*)d_in[2];
    const float* Wk  = (const float*)d_in[3];
    const float* We  = (const float*)d_in[4];
    const float* Wv  = (const float*)d_in[5];
    const int*   ei  = (const int*)d_in[6];
    float* out = (float*)d_out;

    int n  = in_sizes[0] / DIM;   // 100000
    int nE = in_sizes[6] / 2;     // 800000

    init_kernel<<<2048, 256>>>(out, n);

    int qkv_blocks = (n + 31) / 32;   // warp=4 nodes, 8 warps/block
    qkv_kernel<<<qkv_blocks, 256>>>(x, Wq, Wk, Wv, n);

    edge_kernel<<<1480, 256>>>(ea, ei, We, out, nE);

    fin_kernel<<<2048, 256>>>(out, n);
}